// round 4
// baseline (speedup 1.0000x reference)
#include <cuda_runtime.h>
#include <math.h>

// SNN forward: 4 x (GEMM on binary spikes -> fused IIR+LIF scan), final layer
// also emits the output IIR filter. Uses IIR/W commutation: since the
// dual-exp IIR coefficients are identical across features, W @ IIR(s) ==
// IIR(W @ s), so all GEMMs consume raw spike trains.

#define TT 300
#define NB 64

// scratch (device globals: no allocation allowed in kernel_launch)
__device__ float g_cur[NB * 500 * TT];   // 38.4 MB, reused across layers
__device__ float g_s1 [NB * 500 * TT];
__device__ float g_s2 [NB * 200 * TT];
__device__ float g_s3 [NB * 500 * TT];

// ---------------------------------------------------------------------------
// Batched SGEMM: C[b, m, t] = sum_k W[m, k] * S[b, k, t]
//   grid = (ceil(TT/64), ceil(M/64), NB), block = 128 threads
//   Tile 64(M) x 64(N), K-chunk 20 (divides 200/300/500 exactly).
//   Each thread computes an 8(m) x 4(n) register microtile.
// ---------------------------------------------------------------------------
template <int M, int K>
__global__ void __launch_bounds__(128)
gemm_kernel(const float* __restrict__ S,   // [NB, K, TT]
            const float* __restrict__ W,   // [M, K]
            float* __restrict__ C)         // [NB, M, TT]
{
    __shared__ float As[20][68];  // [k][m], padded (68*4 bytes keeps rows 16B-aligned)
    __shared__ float Bs[20][64];  // [k][n]

    const int b   = blockIdx.z;
    const int bm  = blockIdx.y * 64;
    const int bn  = blockIdx.x * 64;
    const int tid = threadIdx.x;
    const int tn  = tid & 15;     // 16 column groups of 4
    const int tm  = tid >> 4;     // 8 row groups of 8

    const float* Sb = S + (size_t)b * K * TT;

    float acc[8][4];
#pragma unroll
    for (int i = 0; i < 8; ++i)
#pragma unroll
        for (int j = 0; j < 4; ++j) acc[i][j] = 0.0f;

    for (int k0 = 0; k0 < K; k0 += 20) {
        // Load W tile (64 m x 20 k), transposed into As[k][m]. 1280 elems / 128 thr.
#pragma unroll
        for (int r = 0; r < 10; ++r) {
            int idx = tid + r * 128;
            int m = idx / 20, kk = idx - m * 20;
            float v = 0.0f;
            if (bm + m < M) v = W[(size_t)(bm + m) * K + (k0 + kk)];
            As[kk][m] = v;
        }
        // Load S tile (20 k x 64 n) into Bs[k][n].
#pragma unroll
        for (int r = 0; r < 10; ++r) {
            int idx = tid + r * 128;
            int kk = idx >> 6, n = idx & 63;
            float v = 0.0f;
            if (bn + n < TT) v = Sb[(size_t)(k0 + kk) * TT + (bn + n)];
            Bs[kk][n] = v;
        }
        __syncthreads();

#pragma unroll
        for (int kk = 0; kk < 20; ++kk) {
            float a[8], bb[4];
#pragma unroll
            for (int i = 0; i < 8; ++i) a[i] = As[kk][tm * 8 + i];
#pragma unroll
            for (int j = 0; j < 4; ++j) bb[j] = Bs[kk][tn * 4 + j];
#pragma unroll
            for (int i = 0; i < 8; ++i)
#pragma unroll
                for (int j = 0; j < 4; ++j)
                    acc[i][j] = fmaf(a[i], bb[j], acc[i][j]);
        }
        __syncthreads();
    }

    // Store. TT % 4 == 0 and tiles start at multiples of 64, so any in-range
    // column group is a fully valid float4.
    float* Cb = C + (size_t)b * M * TT;
    int n0 = bn + tn * 4;
    if (n0 < TT) {
#pragma unroll
        for (int i = 0; i < 8; ++i) {
            int m = bm + tm * 8 + i;
            if (m < M) {
                float4 v = make_float4(acc[i][0], acc[i][1], acc[i][2], acc[i][3]);
                *reinterpret_cast<float4*>(Cb + (size_t)m * TT + n0) = v;
            }
        }
    }
}

// ---------------------------------------------------------------------------
// Fused temporal scan: dual-exp IIR (commuted past W) + LIF with decaying
// reset. One thread per (b, o) row; 300 sequential steps.
//   y[t]  = a1*y[t-1] + a2*y[t-2] + b0*cur[t]
//   v     = y[t] + bias[o] + reset
//   s     = (v >= 1)
//   reset = reset*em - s
// ---------------------------------------------------------------------------
__global__ void scan_lif(const float* __restrict__ Cur,   // [NB, F, TT]
                         const float* __restrict__ a1p,
                         const float* __restrict__ a2p,
                         const float* __restrict__ bp,
                         const float* __restrict__ bias,   // [F]
                         float* __restrict__ Sout,         // [NB, F, TT]
                         int F, float em)
{
    int r = blockIdx.x * blockDim.x + threadIdx.x;
    if (r >= NB * F) return;
    int o = r % F;
    const float a1 = a1p[0], a2 = a2p[0], b0 = bp[0];
    const float bo = bias[o];
    const float* cr = Cur + (size_t)r * TT;
    float* sr = Sout + (size_t)r * TT;

    float y1 = 0.0f, y2 = 0.0f, reset = 0.0f;
    for (int t = 0; t < TT; ++t) {
        float y = a1 * y1 + a2 * y2 + b0 * cr[t];
        y2 = y1; y1 = y;
        float v = y + bo + reset;
        float s = (v >= 1.0f) ? 1.0f : 0.0f;
        reset = reset * em - s;
        sr[t] = s;
    }
}

// Final layer: same scan, but also runs the fixed output dual-exp IIR on the
// spikes and writes both s4 and filt.
__global__ void scan_lif_final(const float* __restrict__ Cur,
                               const float* __restrict__ a1p,
                               const float* __restrict__ a2p,
                               const float* __restrict__ bp,
                               const float* __restrict__ bias,
                               float* __restrict__ Sout,
                               float* __restrict__ Filt,
                               int F, float em,
                               float fa1, float fa2, float fb)
{
    int r = blockIdx.x * blockDim.x + threadIdx.x;
    if (r >= NB * F) return;
    int o = r % F;
    const float a1 = a1p[0], a2 = a2p[0], b0 = bp[0];
    const float bo = bias[o];
    const float* cr = Cur + (size_t)r * TT;
    float* sr = Sout + (size_t)r * TT;
    float* fr = Filt + (size_t)r * TT;

    float y1 = 0.0f, y2 = 0.0f, reset = 0.0f;
    float f1 = 0.0f, f2 = 0.0f;
    for (int t = 0; t < TT; ++t) {
        float y = a1 * y1 + a2 * y2 + b0 * cr[t];
        y2 = y1; y1 = y;
        float v = y + bo + reset;
        float s = (v >= 1.0f) ? 1.0f : 0.0f;
        reset = reset * em - s;
        sr[t] = s;
        float f = fa1 * f1 + fa2 * f2 + fb * s;
        f2 = f1; f1 = f;
        fr[t] = f;
    }
}

// ---------------------------------------------------------------------------
extern "C" void kernel_launch(void* const* d_in, const int* in_sizes, int n_in,
                              void* d_out, int out_size)
{
    const float* inputs = (const float*)d_in[0];
    const float* a1_1 = (const float*)d_in[1];
    const float* a2_1 = (const float*)d_in[2];
    const float* b_1  = (const float*)d_in[3];
    const float* W1   = (const float*)d_in[4];
    const float* bias1= (const float*)d_in[5];
    const float* a1_2 = (const float*)d_in[6];
    const float* a2_2 = (const float*)d_in[7];
    const float* b_2  = (const float*)d_in[8];
    const float* W2   = (const float*)d_in[9];
    const float* bias2= (const float*)d_in[10];
    const float* a1_3 = (const float*)d_in[11];
    const float* a2_3 = (const float*)d_in[12];
    const float* b_3  = (const float*)d_in[13];
    const float* W3   = (const float*)d_in[14];
    const float* bias3= (const float*)d_in[15];
    const float* a1_4 = (const float*)d_in[16];
    const float* a2_4 = (const float*)d_in[17];
    const float* b_4  = (const float*)d_in[18];
    const float* W4   = (const float*)d_in[19];
    const float* bias4= (const float*)d_in[20];

    float* out      = (float*)d_out;
    float* s4_out   = out;                              // [64, 300, 300]
    float* filt_out = out + (size_t)NB * 300 * TT;      // [64, 300, 300]

    float *cur, *s1, *s2, *s3;
    cudaGetSymbolAddress((void**)&cur, g_cur);
    cudaGetSymbolAddress((void**)&s1,  g_s1);
    cudaGetSymbolAddress((void**)&s2,  g_s2);
    cudaGetSymbolAddress((void**)&s3,  g_s3);

    // Output-filter constants, matching the reference's float64->float32 path.
    const double em_d = exp(-1.0 / 8.0), es_d = exp(-1.0 / 2.0);
    const float em  = (float)em_d;
    const float fa1 = (float)(em_d + es_d);
    const float fa2 = (float)(-(em_d * es_d));
    const float fb  = (float)((8.0 / 6.0) * (em_d - es_d));

    const dim3 blk(128);

    // Layer 1: 300 -> 500
    gemm_kernel<500, 300><<<dim3(5, 8, NB), blk>>>(inputs, W1, cur);
    scan_lif<<<(NB * 500 + 255) / 256, 256>>>(cur, a1_1, a2_1, b_1, bias1, s1, 500, em);

    // Layer 2: 500 -> 200
    gemm_kernel<200, 500><<<dim3(5, 4, NB), blk>>>(s1, W2, cur);
    scan_lif<<<(NB * 200 + 255) / 256, 256>>>(cur, a1_2, a2_2, b_2, bias2, s2, 200, em);

    // Layer 3: 200 -> 500
    gemm_kernel<500, 200><<<dim3(5, 8, NB), blk>>>(s2, W3, cur);
    scan_lif<<<(NB * 500 + 255) / 256, 256>>>(cur, a1_3, a2_3, b_3, bias3, s3, 500, em);

    // Layer 4: 500 -> 300, writes s4 + output filter directly into d_out
    gemm_kernel<300, 500><<<dim3(5, 5, NB), blk>>>(s3, W4, cur);
    scan_lif_final<<<(NB * 300 + 255) / 256, 256>>>(cur, a1_4, a2_4, b_4, bias4,
                                                    s4_out, filt_out, 300, em,
                                                    fa1, fa2, fb);
}

// round 6
// speedup vs baseline: 1.2523x; 1.2523x over previous
#include <cuda_runtime.h>
#include <math.h>

// SNN forward: 4 x (GEMM on binary spikes -> fused IIR+LIF scan), final layer
// also emits the output IIR filter. Uses IIR/W commutation: since the
// dual-exp IIR coefficients are identical across features, W @ IIR(s) ==
// IIR(W @ s), so all GEMMs consume raw spike trains.
//
// R4: (a) scans rewritten as coalesced tiled-transpose streaming kernels
//     (b) GEMM double-buffers its smem tiles to hide global-load latency.

#define TT 300
#define NB 64
#define CT 30   // time-chunk for scan tiles (300 = 10 * 30)

// scratch (device globals: no allocation allowed in kernel_launch)
__device__ float g_cur[NB * 500 * TT];   // 38.4 MB, reused across layers
__device__ float g_s1 [NB * 500 * TT];
__device__ float g_s2 [NB * 200 * TT];
__device__ float g_s3 [NB * 500 * TT];

// ---------------------------------------------------------------------------
// Batched SGEMM: C[b, m, t] = sum_k W[m, k] * S[b, k, t]
//   grid = (ceil(TT/64), ceil(M/64), NB), block = 128 threads
//   Tile 64(M) x 64(N), K-chunk 20 (divides 200/300/500 exactly),
//   double-buffered smem. Each thread: 8(m) x 4(n) register microtile.
// ---------------------------------------------------------------------------
template <int M, int K>
__global__ void __launch_bounds__(128)
gemm_kernel(const float* __restrict__ S,   // [NB, K, TT]
            const float* __restrict__ W,   // [M, K]
            float* __restrict__ C)         // [NB, M, TT]
{
    constexpr int NC = K / 20;
    __shared__ float As[2][20][68];  // [buf][k][m], padded rows (16B-aligned)
    __shared__ float Bs[2][20][64];  // [buf][k][n]

    const int b   = blockIdx.z;
    const int bm  = blockIdx.y * 64;
    const int bn  = blockIdx.x * 64;
    const int tid = threadIdx.x;
    const int tn  = tid & 15;     // 16 column groups of 4
    const int tm  = tid >> 4;     // 8 row groups of 8

    const float* Sb = S + (size_t)b * K * TT;

    float acc[8][4];
#pragma unroll
    for (int i = 0; i < 8; ++i)
#pragma unroll
        for (int j = 0; j < 4; ++j) acc[i][j] = 0.0f;

    // prologue: load chunk 0 into buffer 0
    {
#pragma unroll
        for (int r = 0; r < 10; ++r) {
            int idx = tid + r * 128;
            int m = idx / 20, kk = idx - m * 20;
            float v = 0.0f;
            if (bm + m < M) v = W[(size_t)(bm + m) * K + kk];
            As[0][kk][m] = v;
        }
#pragma unroll
        for (int r = 0; r < 10; ++r) {
            int idx = tid + r * 128;
            int kk = idx >> 6, n = idx & 63;
            float v = 0.0f;
            if (bn + n < TT) v = Sb[(size_t)kk * TT + (bn + n)];
            Bs[0][kk][n] = v;
        }
    }
    __syncthreads();

    for (int kc = 0; kc < NC; ++kc) {
        const int cur = kc & 1;
        float wreg[10], sreg[10];
        const bool more = (kc + 1 < NC);

        if (more) {
            int k0 = (kc + 1) * 20;
#pragma unroll
            for (int r = 0; r < 10; ++r) {
                int idx = tid + r * 128;
                int m = idx / 20, kk = idx - m * 20;
                wreg[r] = (bm + m < M) ? W[(size_t)(bm + m) * K + (k0 + kk)] : 0.0f;
            }
#pragma unroll
            for (int r = 0; r < 10; ++r) {
                int idx = tid + r * 128;
                int kk = idx >> 6, n = idx & 63;
                sreg[r] = (bn + n < TT) ? Sb[(size_t)(k0 + kk) * TT + (bn + n)] : 0.0f;
            }
        }

#pragma unroll
        for (int kk = 0; kk < 20; ++kk) {
            float a[8], bb[4];
#pragma unroll
            for (int i = 0; i < 8; ++i) a[i] = As[cur][kk][tm * 8 + i];
#pragma unroll
            for (int j = 0; j < 4; ++j) bb[j] = Bs[cur][kk][tn * 4 + j];
#pragma unroll
            for (int i = 0; i < 8; ++i)
#pragma unroll
                for (int j = 0; j < 4; ++j)
                    acc[i][j] = fmaf(a[i], bb[j], acc[i][j]);
        }

        if (more) {
            const int nxt = cur ^ 1;
#pragma unroll
            for (int r = 0; r < 10; ++r) {
                int idx = tid + r * 128;
                int m = idx / 20, kk = idx - m * 20;
                As[nxt][kk][m] = wreg[r];
            }
#pragma unroll
            for (int r = 0; r < 10; ++r) {
                int idx = tid + r * 128;
                int kk = idx >> 6, n = idx & 63;
                Bs[nxt][kk][n] = sreg[r];
            }
        }
        __syncthreads();
    }

    // Store. Tiles start at multiples of 64; in-range column groups are valid float4.
    float* Cb = C + (size_t)b * M * TT;
    int n0 = bn + tn * 4;
    if (n0 < TT) {
#pragma unroll
        for (int i = 0; i < 8; ++i) {
            int m = bm + tm * 8 + i;
            if (m < M) {
                float4 v = make_float4(acc[i][0], acc[i][1], acc[i][2], acc[i][3]);
                *reinterpret_cast<float4*>(Cb + (size_t)m * TT + n0) = v;
            }
        }
    }
}

// ---------------------------------------------------------------------------
// Fused temporal scan, tiled-transpose version.
// Block = 256 threads = 256 rows (NB*F is always a multiple of 256 here).
// Per 30-step chunk: coalesced load of a 256x30 tile (lane indexes time),
// per-thread scan of its private smem row (bank-conflict-free, stride 31),
// spikes written back through the same tile, coalesced store.
//   y[t]  = a1*y[t-1] + a2*y[t-2] + b0*cur[t]
//   v     = y[t] + bias[o] + reset ;  s = (v >= 1) ;  reset = reset*em - s
// ---------------------------------------------------------------------------
__global__ void __launch_bounds__(256)
scan_lif(const float* __restrict__ Cur,   // [NB, F, TT]
         const float* __restrict__ a1p,
         const float* __restrict__ a2p,
         const float* __restrict__ bp,
         const float* __restrict__ bias,   // [F]
         float* __restrict__ Sout,         // [NB, F, TT]
         int F, float em)
{
    __shared__ float tile[256][CT + 1];

    const int row0 = blockIdx.x * 256;
    const int row  = row0 + threadIdx.x;
    const int o    = row % F;
    const int lane = threadIdx.x & 31;
    const int w    = threadIdx.x >> 5;

    const float a1 = a1p[0], a2 = a2p[0], b0 = bp[0];
    const float bo = bias[o];

    float y1 = 0.0f, y2 = 0.0f, reset = 0.0f;

    for (int t0 = 0; t0 < TT; t0 += CT) {
        // coalesced load: warp w covers rows [w*32, w*32+32)
#pragma unroll
        for (int j = 0; j < 32; ++j) {
            int rr = w * 32 + j;
            if (lane < CT)
                tile[rr][lane] = Cur[(size_t)(row0 + rr) * TT + t0 + lane];
        }
        __syncthreads();

#pragma unroll
        for (int t = 0; t < CT; ++t) {
            float c = tile[threadIdx.x][t];
            float y = a1 * y1 + a2 * y2 + b0 * c;
            y2 = y1; y1 = y;
            float v = y + bo + reset;
            float s = (v >= 1.0f) ? 1.0f : 0.0f;
            reset = reset * em - s;
            tile[threadIdx.x][t] = s;   // overwrite in place (own row)
        }
        __syncthreads();

        // coalesced store of spikes
#pragma unroll
        for (int j = 0; j < 32; ++j) {
            int rr = w * 32 + j;
            if (lane < CT)
                Sout[(size_t)(row0 + rr) * TT + t0 + lane] = tile[rr][lane];
        }
        __syncthreads();
    }
}

// Final layer: also runs the fixed output dual-exp IIR; writes s4 and filt.
__global__ void __launch_bounds__(256)
scan_lif_final(const float* __restrict__ Cur,
               const float* __restrict__ a1p,
               const float* __restrict__ a2p,
               const float* __restrict__ bp,
               const float* __restrict__ bias,
               float* __restrict__ Sout,
               float* __restrict__ Filt,
               int F, float em,
               float fa1, float fa2, float fb)
{
    __shared__ float tile [256][CT + 1];
    __shared__ float ftile[256][CT + 1];

    const int row0 = blockIdx.x * 256;
    const int row  = row0 + threadIdx.x;
    const int o    = row % F;
    const int lane = threadIdx.x & 31;
    const int w    = threadIdx.x >> 5;

    const float a1 = a1p[0], a2 = a2p[0], b0 = bp[0];
    const float bo = bias[o];

    float y1 = 0.0f, y2 = 0.0f, reset = 0.0f;
    float f1 = 0.0f, f2 = 0.0f;

    for (int t0 = 0; t0 < TT; t0 += CT) {
#pragma unroll
        for (int j = 0; j < 32; ++j) {
            int rr = w * 32 + j;
            if (lane < CT)
                tile[rr][lane] = Cur[(size_t)(row0 + rr) * TT + t0 + lane];
        }
        __syncthreads();

#pragma unroll
        for (int t = 0; t < CT; ++t) {
            float c = tile[threadIdx.x][t];
            float y = a1 * y1 + a2 * y2 + b0 * c;
            y2 = y1; y1 = y;
            float v = y + bo + reset;
            float s = (v >= 1.0f) ? 1.0f : 0.0f;
            reset = reset * em - s;
            tile[threadIdx.x][t] = s;
            float f = fa1 * f1 + fa2 * f2 + fb * s;
            f2 = f1; f1 = f;
            ftile[threadIdx.x][t] = f;
        }
        __syncthreads();

#pragma unroll
        for (int j = 0; j < 32; ++j) {
            int rr = w * 32 + j;
            if (lane < CT) {
                size_t off = (size_t)(row0 + rr) * TT + t0 + lane;
                Sout[off] = tile[rr][lane];
                Filt[off] = ftile[rr][lane];
            }
        }
        __syncthreads();
    }
}

// ---------------------------------------------------------------------------
extern "C" void kernel_launch(void* const* d_in, const int* in_sizes, int n_in,
                              void* d_out, int out_size)
{
    const float* inputs = (const float*)d_in[0];
    const float* a1_1 = (const float*)d_in[1];
    const float* a2_1 = (const float*)d_in[2];
    const float* b_1  = (const float*)d_in[3];
    const float* W1   = (const float*)d_in[4];
    const float* bias1= (const float*)d_in[5];
    const float* a1_2 = (const float*)d_in[6];
    const float* a2_2 = (const float*)d_in[7];
    const float* b_2  = (const float*)d_in[8];
    const float* W2   = (const float*)d_in[9];
    const float* bias2= (const float*)d_in[10];
    const float* a1_3 = (const float*)d_in[11];
    const float* a2_3 = (const float*)d_in[12];
    const float* b_3  = (const float*)d_in[13];
    const float* W3   = (const float*)d_in[14];
    const float* bias3= (const float*)d_in[15];
    const float* a1_4 = (const float*)d_in[16];
    const float* a2_4 = (const float*)d_in[17];
    const float* b_4  = (const float*)d_in[18];
    const float* W4   = (const float*)d_in[19];
    const float* bias4= (const float*)d_in[20];

    float* out      = (float*)d_out;
    float* s4_out   = out;                              // [64, 300, 300]
    float* filt_out = out + (size_t)NB * 300 * TT;      // [64, 300, 300]

    float *cur, *s1, *s2, *s3;
    cudaGetSymbolAddress((void**)&cur, g_cur);
    cudaGetSymbolAddress((void**)&s1,  g_s1);
    cudaGetSymbolAddress((void**)&s2,  g_s2);
    cudaGetSymbolAddress((void**)&s3,  g_s3);

    // Output-filter constants, matching the reference's float64->float32 path.
    const double em_d = exp(-1.0 / 8.0), es_d = exp(-1.0 / 2.0);
    const float em  = (float)em_d;
    const float fa1 = (float)(em_d + es_d);
    const float fa2 = (float)(-(em_d * es_d));
    const float fb  = (float)((8.0 / 6.0) * (em_d - es_d));

    const dim3 blk(128);

    // Layer 1: 300 -> 500
    gemm_kernel<500, 300><<<dim3(5, 8, NB), blk>>>(inputs, W1, cur);
    scan_lif<<<NB * 500 / 256, 256>>>(cur, a1_1, a2_1, b_1, bias1, s1, 500, em);

    // Layer 2: 500 -> 200
    gemm_kernel<200, 500><<<dim3(5, 4, NB), blk>>>(s1, W2, cur);
    scan_lif<<<NB * 200 / 256, 256>>>(cur, a1_2, a2_2, b_2, bias2, s2, 200, em);

    // Layer 3: 200 -> 500
    gemm_kernel<500, 200><<<dim3(5, 8, NB), blk>>>(s2, W3, cur);
    scan_lif<<<NB * 500 / 256, 256>>>(cur, a1_3, a2_3, b_3, bias3, s3, 500, em);

    // Layer 4: 500 -> 300, writes s4 + output filter directly into d_out
    gemm_kernel<300, 500><<<dim3(5, 5, NB), blk>>>(s3, W4, cur);
    scan_lif_final<<<NB * 300 / 256, 256>>>(cur, a1_4, a2_4, b_4, bias4,
                                            s4_out, filt_out, 300, em,
                                            fa1, fa2, fb);
}